// round 10
// baseline (speedup 1.0000x reference)
#include <cuda_runtime.h>
#include <cuda_bf16.h>
#include <cstdint>

#define S_LEN 2048
#define HEADS 8
#define BATCH 2
#define DHEAD 128
#define BM 128
#define BN 64
#define NJT (S_LEN / BN)
#define THREADS 512

// smem byte regions (tiles: row stride 256B = 128 bf16 cols)
#define SM_QHI 0
#define SM_QLO 32768
#define SM_K 65536   // + buf*32768 : hi, +16384 : lo
#define SM_V 131072  // hi, +16384 : lo
#define SMEM_TOTAL 163840
// reduction area reuses [0, 67584) after main loop; row stride 132 floats
#define RED_STRIDE 132

__device__ float g_rnorm[HEADS * S_LEN];

__device__ __forceinline__ uint32_t smem_u32(const void* p) {
    uint32_t a;
    asm("{ .reg .u64 t; cvta.to.shared.u64 t, %1; cvt.u32.u64 %0, t; }" : "=r"(a) : "l"(p));
    return a;
}

// pack (e0,e1) -> bf16x2 hi (lo-half=e0), residual bf16x2 lo
__device__ __forceinline__ void split2(float e0, float e1, uint32_t& hi, uint32_t& lo) {
    asm("cvt.rn.bf16x2.f32 %0, %1, %2;" : "=r"(hi) : "f"(e1), "f"(e0));
    float f0 = __uint_as_float(hi << 16);
    float f1 = __uint_as_float(hi & 0xffff0000u);
    asm("cvt.rn.bf16x2.f32 %0, %1, %2;" : "=r"(lo) : "f"(e1 - f1), "f"(e0 - f0));
}

__device__ __forceinline__ void ldmx4(uint32_t& r0, uint32_t& r1, uint32_t& r2, uint32_t& r3,
                                      uint32_t a) {
    asm volatile("ldmatrix.sync.aligned.m8n8.x4.shared.b16 {%0,%1,%2,%3}, [%4];"
                 : "=r"(r0), "=r"(r1), "=r"(r2), "=r"(r3) : "r"(a));
}
__device__ __forceinline__ void ldmx4t(uint32_t& r0, uint32_t& r1, uint32_t& r2, uint32_t& r3,
                                       uint32_t a) {
    asm volatile("ldmatrix.sync.aligned.m8n8.x4.trans.shared.b16 {%0,%1,%2,%3}, [%4];"
                 : "=r"(r0), "=r"(r1), "=r"(r2), "=r"(r3) : "r"(a));
}

__device__ __forceinline__ void mmab(float* c, const uint32_t* a, uint32_t b0, uint32_t b1) {
    asm volatile(
        "mma.sync.aligned.m16n8k16.row.col.f32.bf16.bf16.f32 "
        "{%0,%1,%2,%3},{%4,%5,%6,%7},{%8,%9},{%0,%1,%2,%3};"
        : "+f"(c[0]), "+f"(c[1]), "+f"(c[2]), "+f"(c[3])
        : "r"(a[0]), "r"(a[1]), "r"(a[2]), "r"(a[3]), "r"(b0), "r"(b1));
}

// ---------------- rnorm: rsqrt(sum_j omask[h,i,j]) ----------------
__global__ void rnorm_kernel(const float* __restrict__ omask) {
    int row = blockIdx.x;
    const float* p = omask + (size_t)row * S_LEN;
    float s = 0.f;
    for (int j = threadIdx.x * 4; j < S_LEN; j += 256 * 4) {
        float4 f = *(const float4*)(p + j);
        s += f.x + f.y + f.z + f.w;
    }
#pragma unroll
    for (int off = 16; off > 0; off >>= 1) s += __shfl_xor_sync(0xffffffffu, s, off);
    __shared__ float red[8];
    if ((threadIdx.x & 31) == 0) red[threadIdx.x >> 5] = s;
    __syncthreads();
    if (threadIdx.x == 0) {
        float t = 0.f;
#pragma unroll
        for (int i = 0; i < 8; i++) t += red[i];
        g_rnorm[row] = (t > 0.f) ? rsqrtf(t) : 0.f;
    }
}

// direct LDG->split->STS of a 64x128 fp32 tile into hi/lo bf16 smem (swizzled)
__device__ __forceinline__ void load_tile(const float* __restrict__ src, char* hi, char* lo,
                                          int tid) {
#pragma unroll
    for (int i = 0; i < 4; i++) {
        int x = tid + i * THREADS;
        int r = x >> 5, c4 = (x & 31) << 2;
        float4 f = *(const float4*)(src + r * DHEAD + c4);
        uint32_t h0, l0, h1, l1;
        split2(f.x, f.y, h0, l0);
        split2(f.z, f.w, h1, l1);
        int off = r * 256 + ((((c4 >> 3)) ^ (r & 7)) << 4) + (c4 & 7) * 2;
        *(uint2*)(hi + off) = make_uint2(h0, h1);
        *(uint2*)(lo + off) = make_uint2(l0, l1);
    }
}

__global__ __launch_bounds__(THREADS, 1)
void retention_mma_kernel(const float* __restrict__ q, const float* __restrict__ k,
                          const float* __restrict__ v, const float* __restrict__ omask,
                          float* __restrict__ out) {
    extern __shared__ char smc[];
    const uint32_t su = smem_u32(smc);
    const int tid = threadIdx.x;
    const int wid = tid >> 5, lane = tid & 31;
    const int mw = wid >> 1, jw = wid & 1;  // 8 m-positions x 2 j-halves
    const int m0 = mw * 16;
    const int g = lane >> 2;

    const int it = blockIdx.x, h = blockIdx.y, b = blockIdx.z;
    const int i0 = it * BM;
    const size_t bh = (size_t)(b * HEADS + h);
    const float* qbase = q + (bh * S_LEN + i0) * DHEAD;
    const float* kbase = k + bh * S_LEN * DHEAD;
    const float* vbase = v + bh * S_LEN * DHEAD;
    const float* mbase = omask + ((size_t)h * S_LEN + i0) * S_LEN;

    // ---- Q tile [128x128] -> bf16 hi/lo ----
#pragma unroll
    for (int i = 0; i < 8; i++) {
        int x = tid + i * THREADS;
        int r = x >> 5, c4 = (x & 31) << 2;
        float4 f = *(const float4*)(qbase + r * DHEAD + c4);
        uint32_t h0, l0, h1, l1;
        split2(f.x, f.y, h0, l0);
        split2(f.z, f.w, h1, l1);
        int off = r * 256 + ((((c4 >> 3)) ^ (r & 7)) << 4) + (c4 & 7) * 2;
        *(uint2*)(smc + SM_QHI + off) = make_uint2(h0, h1);
        *(uint2*)(smc + SM_QLO + off) = make_uint2(l0, l1);
    }
    // ---- K/V tile 0 ----
    load_tile(kbase, smc + SM_K, smc + SM_K + 16384, tid);
    load_tile(vbase, smc + SM_V, smc + SM_V + 16384, tid);

    const float rn0 = g_rnorm[h * S_LEN + i0 + m0 + g];
    const float rn1 = g_rnorm[h * S_LEN + i0 + m0 + g + 8];

    float oacc[16][4];  // partial O over this warp's j-half
#pragma unroll
    for (int nt = 0; nt < 16; nt++)
#pragma unroll
        for (int e = 0; e < 4; e++) oacc[nt][e] = 0.f;

    const int qrow = m0 + (lane & 15);
    const int krow_b = (lane & 7) + ((lane >> 4) << 3);

    __syncthreads();

    for (int jt = 0; jt < NJT; jt++) {
        const int buf = jt & 1;
        const bool pf = (jt + 1 < NJT);
        const uint32_t khb = su + SM_K + buf * 32768, klb = khb + 16384;
        const uint32_t vhb = su + SM_V, vlb = vhb + 16384;

        // ---- K LDG (next tile) ----
        float4 kreg[4];
        if (pf) {
            const float* kbn = kbase + (size_t)(jt + 1) * BN * DHEAD;
#pragma unroll
            for (int i = 0; i < 4; i++) {
                int x = tid + i * THREADS;
                kreg[i] = *(const float4*)(kbn + (x >> 5) * DHEAD + ((x & 31) << 2));
            }
        }
        // ---- mask (this warp's j32 half, rn folded) ----
        const float* mp =
            mbase + (size_t)(m0 + g) * S_LEN + jt * BN + jw * 32 + (lane & 3) * 2;
        float2 mk0[4], mk1[4];
#pragma unroll
        for (int nt = 0; nt < 4; nt++) {
            float2 t0 = *(const float2*)(mp + nt * 8);
            float2 t1 = *(const float2*)(mp + 8 * S_LEN + nt * 8);
            mk0[nt] = make_float2(t0.x * rn0, t0.y * rn0);
            mk1[nt] = make_float2(t1.x * rn1, t1.y * rn1);
        }

        // ---- GEMM1: S[m16][j32 of this half] = Q @ K^T (bf16x3) ----
        float sacc[4][4];
#pragma unroll
        for (int nt = 0; nt < 4; nt++)
#pragma unroll
            for (int e = 0; e < 4; e++) sacc[nt][e] = 0.f;
#pragma unroll
        for (int ks = 0; ks < 8; ks++) {
            uint32_t qoff = qrow * 256 + (((2 * ks + (lane >> 4)) ^ (qrow & 7)) << 4);
            uint32_t qh[4], ql[4];
            ldmx4(qh[0], qh[1], qh[2], qh[3], su + SM_QHI + qoff);
            ldmx4(ql[0], ql[1], ql[2], ql[3], su + SM_QLO + qoff);
#pragma unroll
            for (int np = 0; np < 2; np++) {
                int krow = (2 * jw + np) * 16 + krow_b;
                uint32_t koff =
                    krow * 256 + (((2 * ks + ((lane >> 3) & 1)) ^ (krow & 7)) << 4);
                uint32_t h0, h1, h2, h3, l0, l1, l2, l3;
                ldmx4(h0, h1, h2, h3, khb + koff);
                ldmx4(l0, l1, l2, l3, klb + koff);
                mmab(sacc[2 * np], qh, h0, h1);
                mmab(sacc[2 * np + 1], qh, h2, h3);
                mmab(sacc[2 * np], qh, l0, l1);
                mmab(sacc[2 * np + 1], qh, l2, l3);
                mmab(sacc[2 * np], ql, h0, h1);
                mmab(sacc[2 * np + 1], ql, h2, h3);
            }
        }
        // ---- K STS (LDG long done) ----
        if (pf) {
            char* khn = smc + SM_K + (buf ^ 1) * 32768;
#pragma unroll
            for (int i = 0; i < 4; i++) {
                int x = tid + i * THREADS;
                int r = x >> 5, c4 = (x & 31) << 2;
                uint32_t h0, l0, h1, l1;
                split2(kreg[i].x, kreg[i].y, h0, l0);
                split2(kreg[i].z, kreg[i].w, h1, l1);
                int off = r * 256 + ((((c4 >> 3)) ^ (r & 7)) << 4) + (c4 & 7) * 2;
                *(uint2*)(khn + off) = make_uint2(h0, h1);
                *(uint2*)(khn + 16384 + off) = make_uint2(l0, l1);
            }
        }
        // ---- V LDG (next tile) ----
        float4 vreg[4];
        if (pf) {
            const float* vbn = vbase + (size_t)(jt + 1) * BN * DHEAD;
#pragma unroll
            for (int i = 0; i < 4; i++) {
                int x = tid + i * THREADS;
                vreg[i] = *(const float4*)(vbn + (x >> 5) * DHEAD + ((x & 31) << 2));
            }
        }
        // ---- epilogue: sacc *= mask*rn ----
#pragma unroll
        for (int nt = 0; nt < 4; nt++) {
            sacc[nt][0] *= mk0[nt].x;
            sacc[nt][1] *= mk0[nt].y;
            sacc[nt][2] *= mk1[nt].x;
            sacc[nt][3] *= mk1[nt].y;
        }
        // ---- GEMM2: partial O += S @ V over this j-half (kt = 2jw..2jw+1) ----
#pragma unroll
        for (int ktl = 0; ktl < 2; ktl++) {
            uint32_t ah[4], al[4];
            split2(sacc[2 * ktl][0], sacc[2 * ktl][1], ah[0], al[0]);
            split2(sacc[2 * ktl][2], sacc[2 * ktl][3], ah[1], al[1]);
            split2(sacc[2 * ktl + 1][0], sacc[2 * ktl + 1][1], ah[2], al[2]);
            split2(sacc[2 * ktl + 1][2], sacc[2 * ktl + 1][3], ah[3], al[3]);
            const int vrow = (2 * jw + ktl) * 16 + (lane & 15);
#pragma unroll
            for (int np = 0; np < 8; np++) {
                uint32_t voff = vrow * 256 + (((2 * np + (lane >> 4)) ^ (vrow & 7)) << 4);
                uint32_t h0, h1, h2, h3, l0, l1, l2, l3;
                ldmx4t(h0, h1, h2, h3, vhb + voff);
                ldmx4t(l0, l1, l2, l3, vlb + voff);
                mmab(oacc[2 * np], ah, h0, h1);
                mmab(oacc[2 * np + 1], ah, h2, h3);
                mmab(oacc[2 * np], ah, l0, l1);
                mmab(oacc[2 * np + 1], ah, l2, l3);
                mmab(oacc[2 * np], al, h0, h1);
                mmab(oacc[2 * np + 1], al, h2, h3);
            }
        }

        // ---- rotate V buffer ----
        __syncthreads();
        if (pf) {
            char* vh = smc + SM_V;
#pragma unroll
            for (int i = 0; i < 4; i++) {
                int x = tid + i * THREADS;
                int r = x >> 5, c4 = (x & 31) << 2;
                uint32_t h0, l0, h1, l1;
                split2(vreg[i].x, vreg[i].y, h0, l0);
                split2(vreg[i].z, vreg[i].w, h1, l1);
                int off = r * 256 + ((((c4 >> 3)) ^ (r & 7)) << 4) + (c4 & 7) * 2;
                *(uint2*)(vh + off) = make_uint2(h0, h1);
                *(uint2*)(vh + 16384 + off) = make_uint2(l0, l1);
            }
        }
        __syncthreads();
    }

    // ---- cross-warp O reduction (jw=1 -> smem, jw=0 adds) ----
    float* red = (float*)smc;  // reuse Q/K area; [mw][row 0..15][RED_STRIDE]
    float* rbase = red + mw * 16 * RED_STRIDE;
    __syncthreads();
    if (jw == 1) {
        float* r0 = rbase + g * RED_STRIDE + (lane & 3) * 2;
        float* r1 = rbase + (g + 8) * RED_STRIDE + (lane & 3) * 2;
#pragma unroll
        for (int nt = 0; nt < 16; nt++) {
            *(float2*)(r0 + nt * 8) = make_float2(oacc[nt][0], oacc[nt][1]);
            *(float2*)(r1 + nt * 8) = make_float2(oacc[nt][2], oacc[nt][3]);
        }
    }
    __syncthreads();
    if (jw == 0) {
        const float* r0 = rbase + g * RED_STRIDE + (lane & 3) * 2;
        const float* r1 = rbase + (g + 8) * RED_STRIDE + (lane & 3) * 2;
#pragma unroll
        for (int nt = 0; nt < 16; nt++) {
            float2 a = *(const float2*)(r0 + nt * 8);
            float2 b2 = *(const float2*)(r1 + nt * 8);
            oacc[nt][0] += a.x;
            oacc[nt][1] += a.y;
            oacc[nt][2] += b2.x;
            oacc[nt][3] += b2.y;
        }

        // ---- RMSNorm + store ----
        float p0 = 0.f, p1 = 0.f;
#pragma unroll
        for (int nt = 0; nt < 16; nt++) {
            p0 += oacc[nt][0] * oacc[nt][0] + oacc[nt][1] * oacc[nt][1];
            p1 += oacc[nt][2] * oacc[nt][2] + oacc[nt][3] * oacc[nt][3];
        }
        p0 += __shfl_xor_sync(0xffffffffu, p0, 1);
        p0 += __shfl_xor_sync(0xffffffffu, p0, 2);
        p1 += __shfl_xor_sync(0xffffffffu, p1, 1);
        p1 += __shfl_xor_sync(0xffffffffu, p1, 2);
        float sc0 = rsqrtf(p0 * (1.f / 128.f) + 1e-6f);
        float sc1 = rsqrtf(p1 * (1.f / 128.f) + 1e-6f);
        float* o0 = out + (bh * S_LEN + i0 + m0 + g) * DHEAD + (lane & 3) * 2;
        float* o1 = o0 + 8 * DHEAD;
#pragma unroll
        for (int nt = 0; nt < 16; nt++) {
            *(float2*)(o0 + nt * 8) = make_float2(oacc[nt][0] * sc0, oacc[nt][1] * sc0);
            *(float2*)(o1 + nt * 8) = make_float2(oacc[nt][2] * sc1, oacc[nt][3] * sc1);
        }
    }
}

extern "C" void kernel_launch(void* const* d_in, const int* in_sizes, int n_in,
                              void* d_out, int out_size) {
    const float* q = (const float*)d_in[0];
    const float* k = (const float*)d_in[1];
    const float* v = (const float*)d_in[2];
    const float* omask = (const float*)d_in[3];
    float* out = (float*)d_out;

    cudaFuncSetAttribute(retention_mma_kernel, cudaFuncAttributeMaxDynamicSharedMemorySize,
                         SMEM_TOTAL);

    rnorm_kernel<<<HEADS * S_LEN, 256>>>(omask);
    retention_mma_kernel<<<dim3(S_LEN / BM, HEADS, BATCH), THREADS, SMEM_TOTAL>>>(
        q, k, v, omask, out);
}

// round 11
// speedup vs baseline: 1.2661x; 1.2661x over previous
#include <cuda_runtime.h>
#include <cuda_bf16.h>
#include <cstdint>

#define S_LEN 2048
#define HEADS 8
#define BATCH 2
#define DHEAD 128
#define BM 128
#define BN 64
#define NJT (S_LEN / BN)
#define THREADS 512

// smem byte regions (tiles: row stride 256B = 128 bf16 cols)
#define SM_QHI 0
#define SM_QLO 32768
#define SM_KH 65536   // + buf*16384
#define SM_KL 98304   // + buf*16384
#define SM_VH 131072  // + buf*16384
#define SM_VL 163840  // + buf*16384
#define SMEM_TOTAL 196608
#define RED_STRIDE 132

#define NROWS (BATCH * HEADS * S_LEN)  // 32768 rows of 128 elements

// pre-split bf16 hi/lo of K and V, row-major [row][128] (16 uint4 per row)
__device__ uint4 g_kh[NROWS * 16];
__device__ uint4 g_kl[NROWS * 16];
__device__ uint4 g_vh[NROWS * 16];
__device__ uint4 g_vl[NROWS * 16];
__device__ float g_rnorm[HEADS * S_LEN];

__device__ __forceinline__ uint32_t smem_u32(const void* p) {
    uint32_t a;
    asm("{ .reg .u64 t; cvta.to.shared.u64 t, %1; cvt.u32.u64 %0, t; }" : "=r"(a) : "l"(p));
    return a;
}

// pack (e0,e1) -> bf16x2 hi (lo-half=e0), residual bf16x2 lo
__device__ __forceinline__ void split2(float e0, float e1, uint32_t& hi, uint32_t& lo) {
    asm("cvt.rn.bf16x2.f32 %0, %1, %2;" : "=r"(hi) : "f"(e1), "f"(e0));
    float f0 = __uint_as_float(hi << 16);
    float f1 = __uint_as_float(hi & 0xffff0000u);
    asm("cvt.rn.bf16x2.f32 %0, %1, %2;" : "=r"(lo) : "f"(e1 - f1), "f"(e0 - f0));
}

__device__ __forceinline__ void cpa16(uint32_t dst, const void* src) {
    asm volatile("cp.async.cg.shared.global [%0], [%1], 16;" :: "r"(dst), "l"(src));
}

__device__ __forceinline__ void ldmx4(uint32_t& r0, uint32_t& r1, uint32_t& r2, uint32_t& r3,
                                      uint32_t a) {
    asm volatile("ldmatrix.sync.aligned.m8n8.x4.shared.b16 {%0,%1,%2,%3}, [%4];"
                 : "=r"(r0), "=r"(r1), "=r"(r2), "=r"(r3) : "r"(a));
}
__device__ __forceinline__ void ldmx4t(uint32_t& r0, uint32_t& r1, uint32_t& r2, uint32_t& r3,
                                       uint32_t a) {
    asm volatile("ldmatrix.sync.aligned.m8n8.x4.trans.shared.b16 {%0,%1,%2,%3}, [%4];"
                 : "=r"(r0), "=r"(r1), "=r"(r2), "=r"(r3) : "r"(a));
}

__device__ __forceinline__ void mmab(float* c, const uint32_t* a, uint32_t b0, uint32_t b1) {
    asm volatile(
        "mma.sync.aligned.m16n8k16.row.col.f32.bf16.bf16.f32 "
        "{%0,%1,%2,%3},{%4,%5,%6,%7},{%8,%9},{%0,%1,%2,%3};"
        : "+f"(c[0]), "+f"(c[1]), "+f"(c[2]), "+f"(c[3])
        : "r"(a[0]), "r"(a[1]), "r"(a[2]), "r"(a[3]), "r"(b0), "r"(b1));
}

// ---------------- prep: split K,V fp32 -> bf16 hi/lo global ----------------
__global__ void split_kernel(const float* __restrict__ k, const float* __restrict__ v) {
    const float* src = blockIdx.y ? v : k;
    uint2* dh = (uint2*)(blockIdx.y ? g_vh : g_kh);
    uint2* dl = (uint2*)(blockIdx.y ? g_vl : g_kl);
    int gid = blockIdx.x * blockDim.x + threadIdx.x;  // float4 index
    float4 f = *(const float4*)(src + gid * 4);
    uint32_t h0, l0, h1, l1;
    split2(f.x, f.y, h0, l0);
    split2(f.z, f.w, h1, l1);
    dh[gid] = make_uint2(h0, h1);
    dl[gid] = make_uint2(l0, l1);
}

// ---------------- rnorm: rsqrt(sum_j omask[h,i,j]) ----------------
__global__ void rnorm_kernel(const float* __restrict__ omask) {
    int row = blockIdx.x;
    const float* p = omask + (size_t)row * S_LEN;
    float s = 0.f;
    for (int j = threadIdx.x * 4; j < S_LEN; j += 256 * 4) {
        float4 f = *(const float4*)(p + j);
        s += f.x + f.y + f.z + f.w;
    }
#pragma unroll
    for (int off = 16; off > 0; off >>= 1) s += __shfl_xor_sync(0xffffffffu, s, off);
    __shared__ float red[8];
    if ((threadIdx.x & 31) == 0) red[threadIdx.x >> 5] = s;
    __syncthreads();
    if (threadIdx.x == 0) {
        float t = 0.f;
#pragma unroll
        for (int i = 0; i < 8; i++) t += red[i];
        g_rnorm[row] = (t > 0.f) ? rsqrtf(t) : 0.f;
    }
}

__global__ __launch_bounds__(THREADS, 1)
void retention_mma_kernel(const float* __restrict__ q, const float* __restrict__ omask,
                          float* __restrict__ out) {
    extern __shared__ char smc[];
    const uint32_t su = smem_u32(smc);
    const int tid = threadIdx.x;
    const int wid = tid >> 5, lane = tid & 31;
    const int mw = wid >> 1, jw = wid & 1;  // 8 m-positions x 2 j-halves
    const int m0 = mw * 16;
    const int g = lane >> 2;

    const int it = blockIdx.x, h = blockIdx.y, b = blockIdx.z;
    const int i0 = it * BM;
    const size_t bh = (size_t)(b * HEADS + h);
    const float* qbase = q + (bh * S_LEN + i0) * DHEAD;
    const float* mbase = omask + ((size_t)h * S_LEN + i0) * S_LEN;
    const char* gkh = (const char*)g_kh + bh * S_LEN * 256;
    const char* gkl = (const char*)g_kl + bh * S_LEN * 256;
    const char* gvh = (const char*)g_vh + bh * S_LEN * 256;
    const char* gvl = (const char*)g_vl + bh * S_LEN * 256;

    // ---- issue K/V tile 0 via cp.async (group 0) ----
#pragma unroll
    for (int i = 0; i < 2; i++) {
        int x = tid + i * THREADS;  // chunk 0..1023
        int r = x >> 4, c = x & 15;
        uint32_t sw = r * 256 + ((c ^ (r & 7)) << 4);
        size_t go = (size_t)r * 256 + c * 16;
        cpa16(su + SM_KH + sw, gkh + go);
        cpa16(su + SM_KL + sw, gkl + go);
        cpa16(su + SM_VH + sw, gvh + go);
        cpa16(su + SM_VL + sw, gvl + go);
    }
    asm volatile("cp.async.commit_group;" ::: "memory");

    // ---- Q tile [128x128] -> bf16 hi/lo (fp32 path, once) ----
#pragma unroll
    for (int i = 0; i < 8; i++) {
        int x = tid + i * THREADS;
        int r = x >> 5, c4 = (x & 31) << 2;
        float4 f = *(const float4*)(qbase + r * DHEAD + c4);
        uint32_t h0, l0, h1, l1;
        split2(f.x, f.y, h0, l0);
        split2(f.z, f.w, h1, l1);
        int off = r * 256 + ((((c4 >> 3)) ^ (r & 7)) << 4) + (c4 & 7) * 2;
        *(uint2*)(smc + SM_QHI + off) = make_uint2(h0, h1);
        *(uint2*)(smc + SM_QLO + off) = make_uint2(l0, l1);
    }

    const float rn0 = g_rnorm[h * S_LEN + i0 + m0 + g];
    const float rn1 = g_rnorm[h * S_LEN + i0 + m0 + g + 8];

    float oacc[16][4];  // partial O over this warp's j-half
#pragma unroll
    for (int nt = 0; nt < 16; nt++)
#pragma unroll
        for (int e = 0; e < 4; e++) oacc[nt][e] = 0.f;

    const int qrow = m0 + (lane & 15);
    const int krow_b = (lane & 7) + ((lane >> 4) << 3);

    for (int jt = 0; jt < NJT; jt++) {
        const int buf = jt & 1;
        __syncthreads();  // all reads of prev tiles done

        // ---- issue next K/V tiles into buf^1 ----
        if (jt + 1 < NJT) {
            size_t rb = (size_t)(jt + 1) * BN * 256;
            uint32_t sb = (buf ^ 1) * 16384;
#pragma unroll
            for (int i = 0; i < 2; i++) {
                int x = tid + i * THREADS;
                int r = x >> 4, c = x & 15;
                uint32_t sw = r * 256 + ((c ^ (r & 7)) << 4) + sb;
                size_t go = rb + (size_t)r * 256 + c * 16;
                cpa16(su + SM_KH + sw, gkh + go);
                cpa16(su + SM_KL + sw, gkl + go);
                cpa16(su + SM_VH + sw, gvh + go);
                cpa16(su + SM_VL + sw, gvl + go);
            }
        }
        asm volatile("cp.async.commit_group;" ::: "memory");

        // ---- mask LDG (this warp's j32 half, rn folded later) ----
        const float* mp =
            mbase + (size_t)(m0 + g) * S_LEN + jt * BN + jw * 32 + (lane & 3) * 2;
        float2 mk0[4], mk1[4];
#pragma unroll
        for (int nt = 0; nt < 4; nt++) {
            mk0[nt] = *(const float2*)(mp + nt * 8);
            mk1[nt] = *(const float2*)(mp + 8 * S_LEN + nt * 8);
        }

        asm volatile("cp.async.wait_group 1;" ::: "memory");
        __syncthreads();  // current tiles visible to all

        const uint32_t khb = su + SM_KH + buf * 16384, klb = su + SM_KL + buf * 16384;
        const uint32_t vhb = su + SM_VH + buf * 16384, vlb = su + SM_VL + buf * 16384;

        // ---- GEMM1: S[m16][j32 of this half] = Q @ K^T (bf16x3) ----
        float sacc[4][4];
#pragma unroll
        for (int nt = 0; nt < 4; nt++)
#pragma unroll
            for (int e = 0; e < 4; e++) sacc[nt][e] = 0.f;
#pragma unroll
        for (int ks = 0; ks < 8; ks++) {
            uint32_t qoff = qrow * 256 + (((2 * ks + (lane >> 4)) ^ (qrow & 7)) << 4);
            uint32_t qh[4], ql[4];
            ldmx4(qh[0], qh[1], qh[2], qh[3], su + SM_QHI + qoff);
            ldmx4(ql[0], ql[1], ql[2], ql[3], su + SM_QLO + qoff);
#pragma unroll
            for (int np = 0; np < 2; np++) {
                int krow = (2 * jw + np) * 16 + krow_b;
                uint32_t koff =
                    krow * 256 + (((2 * ks + ((lane >> 3) & 1)) ^ (krow & 7)) << 4);
                uint32_t h0, h1, h2, h3, l0, l1, l2, l3;
                ldmx4(h0, h1, h2, h3, khb + koff);
                ldmx4(l0, l1, l2, l3, klb + koff);
                mmab(sacc[2 * np], qh, h0, h1);
                mmab(sacc[2 * np + 1], qh, h2, h3);
                mmab(sacc[2 * np], qh, l0, l1);
                mmab(sacc[2 * np + 1], qh, l2, l3);
                mmab(sacc[2 * np], ql, h0, h1);
                mmab(sacc[2 * np + 1], ql, h2, h3);
            }
        }

        // ---- epilogue: sacc *= mask*rn ----
#pragma unroll
        for (int nt = 0; nt < 4; nt++) {
            sacc[nt][0] *= mk0[nt].x * rn0;
            sacc[nt][1] *= mk0[nt].y * rn0;
            sacc[nt][2] *= mk1[nt].x * rn1;
            sacc[nt][3] *= mk1[nt].y * rn1;
        }

        // ---- GEMM2: partial O += S @ V over this j-half ----
#pragma unroll
        for (int ktl = 0; ktl < 2; ktl++) {
            uint32_t ah[4], al[4];
            split2(sacc[2 * ktl][0], sacc[2 * ktl][1], ah[0], al[0]);
            split2(sacc[2 * ktl][2], sacc[2 * ktl][3], ah[1], al[1]);
            split2(sacc[2 * ktl + 1][0], sacc[2 * ktl + 1][1], ah[2], al[2]);
            split2(sacc[2 * ktl + 1][2], sacc[2 * ktl + 1][3], ah[3], al[3]);
            const int vrow = (2 * jw + ktl) * 16 + (lane & 15);
#pragma unroll
            for (int np = 0; np < 8; np++) {
                uint32_t voff = vrow * 256 + (((2 * np + (lane >> 4)) ^ (vrow & 7)) << 4);
                uint32_t h0, h1, h2, h3, l0, l1, l2, l3;
                ldmx4t(h0, h1, h2, h3, vhb + voff);
                ldmx4t(l0, l1, l2, l3, vlb + voff);
                mmab(oacc[2 * np], ah, h0, h1);
                mmab(oacc[2 * np + 1], ah, h2, h3);
                mmab(oacc[2 * np], ah, l0, l1);
                mmab(oacc[2 * np + 1], ah, l2, l3);
                mmab(oacc[2 * np], al, h0, h1);
                mmab(oacc[2 * np + 1], al, h2, h3);
            }
        }
    }

    // ---- cross-warp O reduction (jw=1 -> smem, jw=0 adds) ----
    float* red = (float*)smc;  // smem reused; [mw][row 0..15][RED_STRIDE]
    float* rbase = red + mw * 16 * RED_STRIDE;
    __syncthreads();
    if (jw == 1) {
        float* r0 = rbase + g * RED_STRIDE + (lane & 3) * 2;
        float* r1 = rbase + (g + 8) * RED_STRIDE + (lane & 3) * 2;
#pragma unroll
        for (int nt = 0; nt < 16; nt++) {
            *(float2*)(r0 + nt * 8) = make_float2(oacc[nt][0], oacc[nt][1]);
            *(float2*)(r1 + nt * 8) = make_float2(oacc[nt][2], oacc[nt][3]);
        }
    }
    __syncthreads();
    if (jw == 0) {
        const float* r0 = rbase + g * RED_STRIDE + (lane & 3) * 2;
        const float* r1 = rbase + (g + 8) * RED_STRIDE + (lane & 3) * 2;
#pragma unroll
        for (int nt = 0; nt < 16; nt++) {
            float2 a = *(const float2*)(r0 + nt * 8);
            float2 b2 = *(const float2*)(r1 + nt * 8);
            oacc[nt][0] += a.x;
            oacc[nt][1] += a.y;
            oacc[nt][2] += b2.x;
            oacc[nt][3] += b2.y;
        }

        // ---- RMSNorm + store ----
        float p0 = 0.f, p1 = 0.f;
#pragma unroll
        for (int nt = 0; nt < 16; nt++) {
            p0 += oacc[nt][0] * oacc[nt][0] + oacc[nt][1] * oacc[nt][1];
            p1 += oacc[nt][2] * oacc[nt][2] + oacc[nt][3] * oacc[nt][3];
        }
        p0 += __shfl_xor_sync(0xffffffffu, p0, 1);
        p0 += __shfl_xor_sync(0xffffffffu, p0, 2);
        p1 += __shfl_xor_sync(0xffffffffu, p1, 1);
        p1 += __shfl_xor_sync(0xffffffffu, p1, 2);
        float sc0 = rsqrtf(p0 * (1.f / 128.f) + 1e-6f);
        float sc1 = rsqrtf(p1 * (1.f / 128.f) + 1e-6f);
        float* o0 = out + (bh * S_LEN + i0 + m0 + g) * DHEAD + (lane & 3) * 2;
        float* o1 = o0 + 8 * DHEAD;
#pragma unroll
        for (int nt = 0; nt < 16; nt++) {
            *(float2*)(o0 + nt * 8) = make_float2(oacc[nt][0] * sc0, oacc[nt][1] * sc0);
            *(float2*)(o1 + nt * 8) = make_float2(oacc[nt][2] * sc1, oacc[nt][3] * sc1);
        }
    }
}

extern "C" void kernel_launch(void* const* d_in, const int* in_sizes, int n_in,
                              void* d_out, int out_size) {
    const float* q = (const float*)d_in[0];
    const float* k = (const float*)d_in[1];
    const float* v = (const float*)d_in[2];
    const float* omask = (const float*)d_in[3];
    float* out = (float*)d_out;

    cudaFuncSetAttribute(retention_mma_kernel, cudaFuncAttributeMaxDynamicSharedMemorySize,
                         SMEM_TOTAL);

    split_kernel<<<dim3(NROWS * 32 / 512, 2), 512>>>(k, v);  // 4 floats/thread
    rnorm_kernel<<<HEADS * S_LEN, 256>>>(omask);
    retention_mma_kernel<<<dim3(S_LEN / BM, HEADS, BATCH), THREADS, SMEM_TOTAL>>>(
        q, omask, out);
}